// round 3
// baseline (speedup 1.0000x reference)
#include <cuda_runtime.h>
#include <math.h>

// ---------------------------------------------------------------------------
// Problem constants (fixed by the reference: B=8, T=4096, D=H=768)
// ---------------------------------------------------------------------------
#define Bn   8
#define Tn   4096
#define Dn   768
#define Hn   768
#define Mn   (Bn * Tn)      // 32768 rows in the fused GEMM
#define BHn  (Bn * Hn)      // 6144 independent scan lanes
#define NCH  64             // number of time chunks for the parallel scan
#define TC   (Tn / NCH)     // 64 timesteps per chunk

// GEMM tiling
#define BM 64
#define BN 64
#define BK 16

// ---------------------------------------------------------------------------
// Device scratch (no cudaMalloc allowed — static device globals)
//   g_a [m, h] : fp_t   (the "a" of the recurrence)
//   g_bv[m, h] : ip_t * h_tilde_t  (the "b" of the recurrence)
// ---------------------------------------------------------------------------
__device__ float g_a [(size_t)Mn * Hn];   // 96 MB
__device__ float g_bv[(size_t)Mn * Hn];   // 96 MB
__device__ float g_cA [NCH * BHn];        // per-chunk A product
__device__ float g_cB [NCH * BHn];        // per-chunk B accumulation
__device__ float g_hin[NCH * BHn];        // h entering each chunk

// ---------------------------------------------------------------------------
// Fused triple GEMM + gating epilogue, double-buffered smem pipeline.
//   acc_f[m,h] = x[m,:] . fw[h,:]   (NT layout: both K-contiguous)
// One X smem tile feeds all three weight tiles (3x smem-bandwidth saving).
// Grid: x walks M (so consecutive CTAs reuse the same weight stripe in L2),
//       y walks H.
// NOTE: smem tiles are padded (stride BK+1) to avoid bank conflicts, so all
// smem STORES must be scalar (a float4 STS to a 17-float-stride row is
// misaligned for odd rows -> HW trap). Global loads stay float4.
// ---------------------------------------------------------------------------
__global__ __launch_bounds__(256, 2) void gemm_fused(
    const float* __restrict__ x,
    const float* __restrict__ fw, const float* __restrict__ fb,
    const float* __restrict__ iw, const float* __restrict__ ib,
    const float* __restrict__ hw, const float* __restrict__ hb)
{
    __shared__ float Xs[2][BM][BK + 1];
    __shared__ float Fs[2][BN][BK + 1];
    __shared__ float Is[2][BN][BK + 1];
    __shared__ float Hs[2][BN][BK + 1];

    const int tid = threadIdx.x;            // 0..255
    const int bm  = blockIdx.x * BM;        // row (M) tile
    const int bn  = blockIdx.y * BN;        // col (H) tile

    // Cooperative loads: one float4 per thread per tile.
    const int lr = tid >> 2;                // 0..63 (tile row)
    const int lc = (tid & 3) * 4;           // 0,4,8,12 (tile col)

    // Microtile mapping: 16x16 threads, each owns a 4x4 patch (x3 GEMMs)
    const int ty = tid >> 4;
    const int tx = tid & 15;
    const int m0 = ty * 4;
    const int n0 = tx * 4;

    float accF[4][4] = {};
    float accI[4][4] = {};
    float accH[4][4] = {};

    const size_t xrow = (size_t)(bm + lr) * Dn + lc;
    const size_t wrow = (size_t)(bn + lr) * Dn + lc;

    // Helper to scatter a float4 into a padded smem row (scalar stores).
#define STORE4(dst, v)  do { (dst)[0] = (v).x; (dst)[1] = (v).y; \
                             (dst)[2] = (v).z; (dst)[3] = (v).w; } while (0)

    // Prologue: load K-tile 0 into buffer 0.
    {
        float4 xv = *(const float4*)&x [xrow];
        float4 fv = *(const float4*)&fw[wrow];
        float4 iv = *(const float4*)&iw[wrow];
        float4 hv = *(const float4*)&hw[wrow];
        STORE4(&Xs[0][lr][lc], xv);
        STORE4(&Fs[0][lr][lc], fv);
        STORE4(&Is[0][lr][lc], iv);
        STORE4(&Hs[0][lr][lc], hv);
    }
    __syncthreads();

    int buf = 0;
    for (int k0 = 0; k0 < Dn; k0 += BK) {
        const int nk = k0 + BK;
        // Prefetch next K-tile into the alternate buffer (no sync needed:
        // nobody reads buf^1 during this iteration).
        if (nk < Dn) {
            float4 xv = *(const float4*)&x [xrow + nk];
            float4 fv = *(const float4*)&fw[wrow + nk];
            float4 iv = *(const float4*)&iw[wrow + nk];
            float4 hv = *(const float4*)&hw[wrow + nk];
            STORE4(&Xs[buf ^ 1][lr][lc], xv);
            STORE4(&Fs[buf ^ 1][lr][lc], fv);
            STORE4(&Is[buf ^ 1][lr][lc], iv);
            STORE4(&Hs[buf ^ 1][lr][lc], hv);
        }

        #pragma unroll
        for (int kk = 0; kk < BK; kk++) {
            float xr[4], fr[4], ir[4], hr[4];
            #pragma unroll
            for (int i = 0; i < 4; i++) xr[i] = Xs[buf][m0 + i][kk];
            #pragma unroll
            for (int j = 0; j < 4; j++) {
                fr[j] = Fs[buf][n0 + j][kk];
                ir[j] = Is[buf][n0 + j][kk];
                hr[j] = Hs[buf][n0 + j][kk];
            }
            #pragma unroll
            for (int i = 0; i < 4; i++)
                #pragma unroll
                for (int j = 0; j < 4; j++) {
                    accF[i][j] = fmaf(xr[i], fr[j], accF[i][j]);
                    accI[i][j] = fmaf(xr[i], ir[j], accI[i][j]);
                    accH[i][j] = fmaf(xr[i], hr[j], accH[i][j]);
                }
        }
        __syncthreads();   // writes to buf^1 complete AND reads of buf done
        buf ^= 1;
    }
#undef STORE4

    // Epilogue: gating math, write a / bv scratch.
    // base = m*768 + tx*4 -> multiple of 4 floats off a 16B-aligned global:
    // float4 stores are safe here.
    #pragma unroll
    for (int i = 0; i < 4; i++) {
        const int m = bm + m0 + i;
        const size_t base = (size_t)m * Hn + bn + n0;
        float4 av, bv;
        float* ap = &av.x;
        float* bp = &bv.x;
        #pragma unroll
        for (int j = 0; j < 4; j++) {
            const int n = bn + n0 + j;
            float f  = 1.0f / (1.0f + expf(-(accF[i][j] + fb[n])));
            float ii = 1.0f / (1.0f + expf(-(accI[i][j] + ib[n])));
            float ht = accH[i][j] + hb[n];
            float inv = 1.0f / (f + ii + 1e-8f);
            ap[j] = f * inv;
            bp[j] = (ii * inv) * ht;
        }
        *(float4*)&g_a [base] = av;
        *(float4*)&g_bv[base] = bv;
    }
}

// ---------------------------------------------------------------------------
// Scan pass 1: per-chunk reduction. Each thread owns one (b,h) lane within
// one chunk of TC timesteps, computing (A = prod a, B = local scan result).
// Lanes are consecutive h -> fully coalesced.
// ---------------------------------------------------------------------------
__global__ __launch_bounds__(256) void scan_chunk()
{
    const int lane  = blockIdx.x * blockDim.x + threadIdx.x;  // 0..BHn-1
    const int chunk = blockIdx.y;
    const int b = lane / Hn;
    const int h = lane - b * Hn;

    size_t idx = ((size_t)(b * Tn + chunk * TC)) * Hn + h;
    float A = 1.0f, Bc = 0.0f;
    #pragma unroll 4
    for (int t = 0; t < TC; t++) {
        const float a  = g_a [idx];
        const float bb = g_bv[idx];
        Bc = fmaf(a, Bc, bb);
        A *= a;
        idx += Hn;
    }
    g_cA[chunk * BHn + lane] = A;
    g_cB[chunk * BHn + lane] = Bc;
}

// ---------------------------------------------------------------------------
// Scan pass 2: sequential scan over the NCH chunk carries per lane.
// Records the h entering each chunk. h0 is (B,1,H) = BHn floats.
// ---------------------------------------------------------------------------
__global__ __launch_bounds__(256) void scan_carry(const float* __restrict__ h0)
{
    const int lane = blockIdx.x * blockDim.x + threadIdx.x;
    float h = h0[lane];
    #pragma unroll
    for (int c = 0; c < NCH; c++) {
        g_hin[c * BHn + lane] = h;
        h = fmaf(g_cA[c * BHn + lane], h, g_cB[c * BHn + lane]);
    }
}

// ---------------------------------------------------------------------------
// Scan pass 3: re-run each chunk with the correct entering h, emit outputs.
// ---------------------------------------------------------------------------
__global__ __launch_bounds__(256) void scan_apply(float* __restrict__ out)
{
    const int lane  = blockIdx.x * blockDim.x + threadIdx.x;
    const int chunk = blockIdx.y;
    const int b = lane / Hn;
    const int hh = lane - b * Hn;

    float h = g_hin[chunk * BHn + lane];
    size_t idx = ((size_t)(b * Tn + chunk * TC)) * Hn + hh;
    #pragma unroll 4
    for (int t = 0; t < TC; t++) {
        h = fmaf(g_a[idx], h, g_bv[idx]);
        out[idx] = h;
        idx += Hn;
    }
}

// ---------------------------------------------------------------------------
// Launch
// ---------------------------------------------------------------------------
extern "C" void kernel_launch(void* const* d_in, const int* in_sizes, int n_in,
                              void* d_out, int out_size)
{
    const float* x  = (const float*)d_in[0];
    const float* h0 = (const float*)d_in[1];
    const float* fw = (const float*)d_in[2];
    const float* fb = (const float*)d_in[3];
    const float* iw = (const float*)d_in[4];
    const float* ib = (const float*)d_in[5];
    const float* hw = (const float*)d_in[6];
    const float* hb = (const float*)d_in[7];
    float* out = (float*)d_out;

    dim3 gGemm(Mn / BM, Hn / BN);             // (512, 12): x walks M for L2 weight reuse
    gemm_fused<<<gGemm, 256>>>(x, fw, fb, iw, ib, hw, hb);

    dim3 gScan(BHn / 256, NCH);               // (24, 64)
    scan_chunk<<<gScan, 256>>>();
    scan_carry<<<BHn / 256, 256>>>(h0);
    scan_apply<<<gScan, 256>>>(out);
}

// round 5
// speedup vs baseline: 2.6040x; 2.6040x over previous
#include <cuda_runtime.h>
#include <cuda_bf16.h>
#include <math.h>
#include <stdint.h>

// ---------------------------------------------------------------------------
// Problem constants (B=8, T=4096, D=H=768)
// ---------------------------------------------------------------------------
#define Bn   8
#define Tn   4096
#define Dn   768
#define Hn   768
#define Mn   (Bn * Tn)      // 32768
#define BHn  (Bn * Hn)      // 6144 scan lanes
#define NCH  64
#define TC   (Tn / NCH)     // 64

// GEMM tiling
#define TM   128            // CTA M tile
#define TN   64             // CTA N tile
#define BK   32             // K chunk per stage
#define NKI  (Dn / BK)      // 24 iterations

// Padded smem row: 32 halves data + 8 pad = 40 halves = 80 bytes.
// Bank pattern for fragment loads (r*20 + t) mod 32 is conflict-free.
#define ROWB 80
#define A_TILE_B   (TM * ROWB)           // 10240
#define B_TILE_B   (TN * ROWB)           // 5120
#define STG_B      (2 * A_TILE_B + 6 * B_TILE_B)   // 51200
#define SMEM_TOTAL (2 * STG_B)                     // 102400

// ---------------------------------------------------------------------------
// Device scratch
// ---------------------------------------------------------------------------
__device__ float g_a [(size_t)Mn * Hn];
__device__ float g_bv[(size_t)Mn * Hn];
__device__ float g_cA [NCH * BHn];
__device__ float g_cB [NCH * BHn];
__device__ float g_hin[NCH * BHn];

__device__ __nv_bfloat16 g_xhi[(size_t)Mn * Dn];
__device__ __nv_bfloat16 g_xlo[(size_t)Mn * Dn];
__device__ __nv_bfloat16 g_fwhi[Hn * Dn];
__device__ __nv_bfloat16 g_fwlo[Hn * Dn];
__device__ __nv_bfloat16 g_iwhi[Hn * Dn];
__device__ __nv_bfloat16 g_iwlo[Hn * Dn];
__device__ __nv_bfloat16 g_hwhi[Hn * Dn];
__device__ __nv_bfloat16 g_hwlo[Hn * Dn];

// ---------------------------------------------------------------------------
// Helpers
// ---------------------------------------------------------------------------
__device__ __forceinline__ uint32_t smem_u32(const void* p) {
    uint32_t a;
    asm("{ .reg .u64 t; cvta.to.shared.u64 t, %1; cvt.u32.u64 %0, t; }" : "=r"(a) : "l"(p));
    return a;
}
__device__ __forceinline__ uint32_t lds32(uint32_t a) {
    uint32_t v;
    asm("ld.shared.b32 %0, [%1];" : "=r"(v) : "r"(a));
    return v;
}
__device__ __forceinline__ void cpa16(uint32_t dst, const void* src) {
    asm volatile("cp.async.cg.shared.global [%0], [%1], 16;" :: "r"(dst), "l"(src) : "memory");
}
#define CPA_COMMIT() asm volatile("cp.async.commit_group;" ::: "memory")
#define CPA_WAIT1()  asm volatile("cp.async.wait_group 1;" ::: "memory")
#define CPA_WAIT0()  asm volatile("cp.async.wait_group 0;" ::: "memory")

// mma.sync m16n8k16 bf16 * bf16 -> f32, row.col (both operands K-contiguous)
__device__ __forceinline__ void mma16816(float* c, const uint32_t* a, const uint32_t* b) {
    asm volatile(
        "mma.sync.aligned.m16n8k16.row.col.f32.bf16.bf16.f32 "
        "{%0,%1,%2,%3}, {%4,%5,%6,%7}, {%8,%9}, {%0,%1,%2,%3};"
        : "+f"(c[0]), "+f"(c[1]), "+f"(c[2]), "+f"(c[3])
        : "r"(a[0]), "r"(a[1]), "r"(a[2]), "r"(a[3]), "r"(b[0]), "r"(b[1]));
}

// ---------------------------------------------------------------------------
// Split-conversion: fp32 -> (bf16 hi, bf16 lo = bf16(v - hi))
// ---------------------------------------------------------------------------
__global__ void convert_split(const float* __restrict__ in,
                              __nv_bfloat16* __restrict__ hi,
                              __nv_bfloat16* __restrict__ lo, int n4) {
    int i = blockIdx.x * blockDim.x + threadIdx.x;
    if (i >= n4) return;
    float4 v = ((const float4*)in)[i];
    float f[4] = {v.x, v.y, v.z, v.w};
    __nv_bfloat162 h01, h23, l01, l23;
    __nv_bfloat16 h0 = __float2bfloat16(f[0]);
    __nv_bfloat16 h1 = __float2bfloat16(f[1]);
    __nv_bfloat16 h2 = __float2bfloat16(f[2]);
    __nv_bfloat16 h3 = __float2bfloat16(f[3]);
    h01.x = h0; h01.y = h1; h23.x = h2; h23.y = h3;
    l01.x = __float2bfloat16(f[0] - __bfloat162float(h0));
    l01.y = __float2bfloat16(f[1] - __bfloat162float(h1));
    l23.x = __float2bfloat16(f[2] - __bfloat162float(h2));
    l23.y = __float2bfloat16(f[3] - __bfloat162float(h3));
    ((__nv_bfloat162*)hi)[2 * i]     = h01;
    ((__nv_bfloat162*)hi)[2 * i + 1] = h23;
    ((__nv_bfloat162*)lo)[2 * i]     = l01;
    ((__nv_bfloat162*)lo)[2 * i + 1] = l23;
}

// ---------------------------------------------------------------------------
// Triple-GEMM via mma.sync bf16 split + fused gating epilogue.
// Grid: x = H tiles (fast -> weights L2-hot), y = M tiles. Block 256 (8 warps).
// ---------------------------------------------------------------------------
__global__ __launch_bounds__(256, 1) void gemm_mma(
    const float* __restrict__ fb, const float* __restrict__ ib,
    const float* __restrict__ hb)
{
    extern __shared__ __align__(128) char smem[];
    const uint32_t sb = smem_u32(smem);
    const int tid = threadIdx.x;
    const int wid = tid >> 5;
    const int lid = tid & 31;
    const int g   = lid >> 2;      // groupID 0..7
    const int tig = lid & 3;       // thread-in-group
    const int wm  = wid & 3;       // warp M index (0..3) -> rows wm*32
    const int wn  = wid >> 2;      // warp N index (0..1) -> cols wn*32
    const int bn  = blockIdx.x * TN;
    const int bm  = blockIdx.y * TM;

    // ---- stage loader (cp.async) ----
    auto issue_stage = [&](int stage, int k0) {
        const uint32_t s = sb + stage * STG_B;
        // A hi/lo: 128 rows x 4 chunks; 512 chunks each -> 2 per thread
        #pragma unroll
        for (int rr = 0; rr < 2; rr++) {
            int i = tid + rr * 256;
            int row = i >> 2, c = i & 3;
            uint32_t dst = s + row * ROWB + c * 16;
            size_t gi = (size_t)(bm + row) * Dn + k0 + c * 8;
            cpa16(dst,            g_xhi + gi);
            cpa16(dst + A_TILE_B, g_xlo + gi);
        }
        // B tiles: 6 x (64 rows x 4 chunks = 256) -> 1 per thread per tile
        {
            int row = tid >> 2, c = tid & 3;
            uint32_t dstb = s + 2 * A_TILE_B + row * ROWB + c * 16;
            size_t gi = (size_t)(bn + row) * Dn + k0 + c * 8;
            cpa16(dstb + 0 * B_TILE_B, g_fwhi + gi);
            cpa16(dstb + 1 * B_TILE_B, g_fwlo + gi);
            cpa16(dstb + 2 * B_TILE_B, g_iwhi + gi);
            cpa16(dstb + 3 * B_TILE_B, g_iwlo + gi);
            cpa16(dstb + 4 * B_TILE_B, g_hwhi + gi);
            cpa16(dstb + 5 * B_TILE_B, g_hwlo + gi);
        }
    };

    float acc[3][2][4][4];
    #pragma unroll
    for (int p = 0; p < 3; p++)
        #pragma unroll
        for (int mi = 0; mi < 2; mi++)
            #pragma unroll
            for (int ni = 0; ni < 4; ni++)
                #pragma unroll
                for (int q = 0; q < 4; q++) acc[p][mi][ni][q] = 0.0f;

    issue_stage(0, 0);  CPA_COMMIT();
    issue_stage(1, BK); CPA_COMMIT();

    for (int k = 0; k < NKI; k++) {
        if (k < NKI - 2) CPA_WAIT1(); else CPA_WAIT0();
        __syncthreads();

        const uint32_t s = sb + (k & 1) * STG_B;
        #pragma unroll
        for (int ks = 0; ks < 2; ks++) {          // two k16 steps in BK=32
            const uint32_t kOff = ks * 32;        // 16 halves = 32 bytes

            // A fragments (hi & lo), 2 m-tiles
            uint32_t ah[2][4], al[2][4];
            #pragma unroll
            for (int mi = 0; mi < 2; mi++) {
                uint32_t r0 = s + (wm * 32 + mi * 16 + g) * ROWB + kOff + tig * 4;
                ah[mi][0] = lds32(r0);
                ah[mi][1] = lds32(r0 + 8 * ROWB);
                ah[mi][2] = lds32(r0 + 16);
                ah[mi][3] = lds32(r0 + 8 * ROWB + 16);
                uint32_t r1 = r0 + A_TILE_B;
                al[mi][0] = lds32(r1);
                al[mi][1] = lds32(r1 + 8 * ROWB);
                al[mi][2] = lds32(r1 + 16);
                al[mi][3] = lds32(r1 + 8 * ROWB + 16);
            }

            #pragma unroll
            for (int p = 0; p < 3; p++) {
                const uint32_t bh_base = s + 2 * A_TILE_B + (2 * p) * B_TILE_B;
                uint32_t bh[4][2], bl[4][2];
                #pragma unroll
                for (int ni = 0; ni < 4; ni++) {
                    uint32_t r = bh_base + (wn * 32 + ni * 8 + g) * ROWB + kOff + tig * 4;
                    bh[ni][0] = lds32(r);
                    bh[ni][1] = lds32(r + 16);
                    bl[ni][0] = lds32(r + B_TILE_B);
                    bl[ni][1] = lds32(r + B_TILE_B + 16);
                }
                #pragma unroll
                for (int mi = 0; mi < 2; mi++)
                    #pragma unroll
                    for (int ni = 0; ni < 4; ni++) {
                        mma16816(acc[p][mi][ni], ah[mi], bh[ni]);  // hi*hi
                        mma16816(acc[p][mi][ni], ah[mi], bl[ni]);  // hi*lo
                        mma16816(acc[p][mi][ni], al[mi], bh[ni]);  // lo*hi
                    }
            }
        }
        __syncthreads();
        if (k + 2 < NKI) { issue_stage(k & 1, (k + 2) * BK); CPA_COMMIT(); }
    }

    // ---- epilogue: sigmoid gating -> g_a / g_bv ----
    #pragma unroll
    for (int ni = 0; ni < 4; ni++) {
        const int col = bn + wn * 32 + ni * 8 + tig * 2;
        const float fb0 = fb[col], fb1 = fb[col + 1];
        const float ib0 = ib[col], ib1 = ib[col + 1];
        const float hb0 = hb[col], hb1 = hb[col + 1];
        #pragma unroll
        for (int mi = 0; mi < 2; mi++) {
            #pragma unroll
            for (int half = 0; half < 2; half++) {
                const int m = bm + wm * 32 + mi * 16 + g + half * 8;
                const float F0 = acc[0][mi][ni][half * 2 + 0] + fb0;
                const float F1 = acc[0][mi][ni][half * 2 + 1] + fb1;
                const float I0 = acc[1][mi][ni][half * 2 + 0] + ib0;
                const float I1 = acc[1][mi][ni][half * 2 + 1] + ib1;
                const float H0 = acc[2][mi][ni][half * 2 + 0] + hb0;
                const float H1 = acc[2][mi][ni][half * 2 + 1] + hb1;
                const float f0 = 1.0f / (1.0f + expf(-F0));
                const float f1 = 1.0f / (1.0f + expf(-F1));
                const float i0 = 1.0f / (1.0f + expf(-I0));
                const float i1 = 1.0f / (1.0f + expf(-I1));
                const float v0 = 1.0f / (f0 + i0 + 1e-8f);
                const float v1 = 1.0f / (f1 + i1 + 1e-8f);
                float2 av = make_float2(f0 * v0, f1 * v1);
                float2 bv = make_float2(i0 * v0 * H0, i1 * v1 * H1);
                const size_t base = (size_t)m * Hn + col;
                *(float2*)&g_a [base] = av;
                *(float2*)&g_bv[base] = bv;
            }
        }
    }
}

// ---------------------------------------------------------------------------
// Scan (3-pass chunked), float4-vectorized over h.
// ---------------------------------------------------------------------------
__global__ __launch_bounds__(256) void scan_chunk()
{
    const int lane4 = blockIdx.x * blockDim.x + threadIdx.x;   // 0..BHn/4-1
    const int chunk = blockIdx.y;
    const int h4 = lane4 * 4;
    const int b = h4 / Hn;
    const int h = h4 - b * Hn;

    size_t idx = ((size_t)(b * Tn + chunk * TC)) * Hn + h;
    float4 A = make_float4(1.f, 1.f, 1.f, 1.f);
    float4 Bc = make_float4(0.f, 0.f, 0.f, 0.f);
    #pragma unroll 4
    for (int t = 0; t < TC; t++) {
        float4 a  = *(const float4*)&g_a [idx];
        float4 bb = *(const float4*)&g_bv[idx];
        Bc.x = fmaf(a.x, Bc.x, bb.x); A.x *= a.x;
        Bc.y = fmaf(a.y, Bc.y, bb.y); A.y *= a.y;
        Bc.z = fmaf(a.z, Bc.z, bb.z); A.z *= a.z;
        Bc.w = fmaf(a.w, Bc.w, bb.w); A.w *= a.w;
        idx += Hn;
    }
    *(float4*)&g_cA[chunk * BHn + h4] = A;
    *(float4*)&g_cB[chunk * BHn + h4] = Bc;
}

__global__ __launch_bounds__(256) void scan_carry(const float* __restrict__ h0)
{
    const int lane = blockIdx.x * blockDim.x + threadIdx.x;
    float h = h0[lane];
    #pragma unroll
    for (int c = 0; c < NCH; c++) {
        g_hin[c * BHn + lane] = h;
        h = fmaf(g_cA[c * BHn + lane], h, g_cB[c * BHn + lane]);
    }
}

__global__ __launch_bounds__(256) void scan_apply(float* __restrict__ out)
{
    const int lane4 = blockIdx.x * blockDim.x + threadIdx.x;
    const int chunk = blockIdx.y;
    const int h4 = lane4 * 4;
    const int b = h4 / Hn;
    const int h = h4 - b * Hn;

    float4 hc = *(const float4*)&g_hin[chunk * BHn + h4];
    size_t idx = ((size_t)(b * Tn + chunk * TC)) * Hn + h;
    #pragma unroll 4
    for (int t = 0; t < TC; t++) {
        float4 a  = *(const float4*)&g_a [idx];
        float4 bb = *(const float4*)&g_bv[idx];
        hc.x = fmaf(a.x, hc.x, bb.x);
        hc.y = fmaf(a.y, hc.y, bb.y);
        hc.z = fmaf(a.z, hc.z, bb.z);
        hc.w = fmaf(a.w, hc.w, bb.w);
        *(float4*)&out[idx] = hc;
        idx += Hn;
    }
}

// ---------------------------------------------------------------------------
// Launch
// ---------------------------------------------------------------------------
extern "C" void kernel_launch(void* const* d_in, const int* in_sizes, int n_in,
                              void* d_out, int out_size)
{
    const float* x  = (const float*)d_in[0];
    const float* h0 = (const float*)d_in[1];
    const float* fw = (const float*)d_in[2];
    const float* fb = (const float*)d_in[3];
    const float* iw = (const float*)d_in[4];
    const float* ib = (const float*)d_in[5];
    const float* hw = (const float*)d_in[6];
    const float* hb = (const float*)d_in[7];
    float* out = (float*)d_out;

    static int smem_set = 0;
    if (!smem_set) {
        cudaFuncSetAttribute(gemm_mma, cudaFuncAttributeMaxDynamicSharedMemorySize,
                             SMEM_TOTAL);
        smem_set = 1;
    }

    __nv_bfloat16 *xhi, *xlo, *fwh, *fwl, *iwh, *iwl, *hwh, *hwl;
    cudaGetSymbolAddress((void**)&xhi, g_xhi);
    cudaGetSymbolAddress((void**)&xlo, g_xlo);
    cudaGetSymbolAddress((void**)&fwh, g_fwhi);
    cudaGetSymbolAddress((void**)&fwl, g_fwlo);
    cudaGetSymbolAddress((void**)&iwh, g_iwhi);
    cudaGetSymbolAddress((void**)&iwl, g_iwlo);
    cudaGetSymbolAddress((void**)&hwh, g_hwhi);
    cudaGetSymbolAddress((void**)&hwl, g_hwlo);

    const int n4x = (Mn * Dn) / 4;
    const int n4w = (Hn * Dn) / 4;
    convert_split<<<(n4x + 255) / 256, 256>>>(x,  xhi, xlo, n4x);
    convert_split<<<(n4w + 255) / 256, 256>>>(fw, fwh, fwl, n4w);
    convert_split<<<(n4w + 255) / 256, 256>>>(iw, iwh, iwl, n4w);
    convert_split<<<(n4w + 255) / 256, 256>>>(hw, hwh, hwl, n4w);

    dim3 gGemm(Hn / TN, Mn / TM);   // (12, 256): N fastest -> weights L2-hot
    gemm_mma<<<gGemm, 256, SMEM_TOTAL>>>(fb, ib, hb);

    dim3 gScan((BHn / 4) / 256, NCH);
    scan_chunk<<<gScan, 256>>>();
    scan_carry<<<BHn / 256, 256>>>(h0);
    scan_apply<<<gScan, 256>>>(out);
}